// round 2
// baseline (speedup 1.0000x reference)
#include <cuda_runtime.h>
#include <cstdint>

// Problem constants
#define H8    64
#define W8    64
#define CH    256
#define BATCH 4
#define NPIX  (H8 * W8)          // 4096
#define NL    41                 // diamond taps
#define F2P_PIX 5440             // 4096 + 1024 + 256 + 64 pooled pixels per batch

// Level pixel offsets inside g_f2p (per batch)
#define LVL0_OFF 0
#define LVL1_OFF 4096
#define LVL2_OFF 5120
#define LVL3_OFF 5376

// Scratch: transposed f1 [B][pix][C], pooled+transposed f2 pyramid [B][lvl pix][C]
__device__ __align__(16) float g_f1t[BATCH * NPIX * CH];
__device__ __align__(16) float g_f2p[BATCH * F2P_PIX * CH];

// Diamond offsets (y, x): y=-4..4, x = |y|-4 .. 4-|y|  (41 total)
__constant__ float c_dy[NL] = {
    -4.f,
    -3.f,-3.f,-3.f,
    -2.f,-2.f,-2.f,-2.f,-2.f,
    -1.f,-1.f,-1.f,-1.f,-1.f,-1.f,-1.f,
     0.f, 0.f, 0.f, 0.f, 0.f, 0.f, 0.f, 0.f, 0.f,
     1.f, 1.f, 1.f, 1.f, 1.f, 1.f, 1.f,
     2.f, 2.f, 2.f, 2.f, 2.f,
     3.f, 3.f, 3.f,
     4.f};
__constant__ float c_dx[NL] = {
     0.f,
    -1.f, 0.f, 1.f,
    -2.f,-1.f, 0.f, 1.f, 2.f,
    -3.f,-2.f,-1.f, 0.f, 1.f, 2.f, 3.f,
    -4.f,-3.f,-2.f,-1.f, 0.f, 1.f, 2.f, 3.f, 4.f,
    -3.f,-2.f,-1.f, 0.f, 1.f, 2.f, 3.f,
    -2.f,-1.f, 0.f, 1.f, 2.f,
    -1.f, 0.f, 1.f,
     0.f};

// ---------------------------------------------------------------------------
// Kernel 1: transpose [B][C][4096] -> [B][4096][C]   (which=0 -> g_f1t, 1 -> g_f2p lvl0)
// ---------------------------------------------------------------------------
__global__ void transpose_kernel(const float* __restrict__ in, int which, int out_pix_stride) {
    __shared__ float tile[32][33];
    float* outp = which ? g_f2p : g_f1t;
    int b  = blockIdx.z;
    int p0 = blockIdx.x * 32;
    int c0 = blockIdx.y * 32;
    const float* inb = in + (size_t)b * CH * NPIX;
    float* outb = outp + (size_t)b * out_pix_stride * CH;
    int tx = threadIdx.x, ty = threadIdx.y;
#pragma unroll
    for (int r = 0; r < 32; r += 8)
        tile[ty + r][tx] = inb[(size_t)(c0 + ty + r) * NPIX + (p0 + tx)];
    __syncthreads();
#pragma unroll
    for (int r = 0; r < 32; r += 8)
        outb[(size_t)(p0 + ty + r) * CH + (c0 + tx)] = tile[tx][ty + r];
}

// ---------------------------------------------------------------------------
// Kernel 2: 2x2 avg pool in [y][x][C] layout (within g_f2p), per batch.
// Exact grid: BATCH * ho * ho * 64 threads (one float4 / thread).
// ---------------------------------------------------------------------------
__global__ void pool_kernel(int in_off, int out_off, int ho) {
    int idx = blockIdx.x * blockDim.x + threadIdx.x;
    int c4   = idx & 63;
    int rest = idx >> 6;
    int x = rest % ho; rest /= ho;
    int y = rest % ho;
    int b = rest / ho;
    int wi = ho * 2;
    const float4* inp = (const float4*)g_f2p;
    float4*       out4 = (float4*)g_f2p;
    size_t base = ((size_t)b * F2P_PIX + in_off + (size_t)(2 * y) * wi + 2 * x) * 64 + c4;
    float4 v00 = inp[base];
    float4 v01 = inp[base + 64];
    float4 v10 = inp[base + (size_t)wi * 64];
    float4 v11 = inp[base + (size_t)wi * 64 + 64];
    float4 o;
    o.x = 0.25f * (v00.x + v01.x + v10.x + v11.x);
    o.y = 0.25f * (v00.y + v01.y + v10.y + v11.y);
    o.z = 0.25f * (v00.z + v01.z + v10.z + v11.z);
    o.w = 0.25f * (v00.w + v01.w + v10.w + v11.w);
    out4[((size_t)b * F2P_PIX + out_off + (size_t)y * ho + x) * 64 + c4] = o;
}

// ---------------------------------------------------------------------------
// Kernel 3: fused lookup. One block (256 thr) per (b, i, j) query pixel.
// Phase A: build 10x10 corner dot-product table per level (zero outside grid).
// Phase B: 164 taps bilinearly combine 4 table entries each.
// ---------------------------------------------------------------------------
__global__ void __launch_bounds__(256) lookup_kernel(const float* __restrict__ flow,
                                                     float* __restrict__ out) {
    const int pix  = blockIdx.x;            // 0..4095
    const int b    = blockIdx.y;
    const int i    = pix >> 6;
    const int j    = pix & 63;
    const int tid  = threadIdx.x;
    const int lane = tid & 31;
    const int warp = tid >> 5;

    __shared__ float D[4][100];

    const float fy = flow[((size_t)(b * 2 + 0) * H8 + i) * W8 + j];
    const float fx = flow[((size_t)(b * 2 + 1) * H8 + i) * W8 + j];

    // f1 vector: lane holds channels [4*lane .. 4*lane+3] and [128+4*lane .. +3]
    const float* f1v = g_f1t + ((size_t)b * NPIX + pix) * CH;
    const float4 f1a = *(const float4*)(f1v + lane * 4);
    const float4 f1b = *(const float4*)(f1v + 128 + lane * 4);

    const int lvl_off[4] = {LVL0_OFF, LVL1_OFF, LVL2_OFF, LVL3_OFF};

    // ---- Phase A: corner dot tables ----
    for (int k = 0; k < 4; k++) {
        const int   h   = H8 >> k;
        const float s   = (float)(h - 1) / (float)h;
        const float inv = 1.0f / (float)(1 << k);
        const float ycf = ((float)i + fy) * inv;
        const float xcf = ((float)j + fx) * inv;
        const int ymin = (int)floorf((ycf - 4.0f) * s);
        const int xmin = (int)floorf((xcf - 4.0f) * s);
        const float* base = g_f2p + ((size_t)b * F2P_PIX + lvl_off[k]) * CH;

        for (int corner = warp; corner < 100; corner += 8) {
            const int iy = corner / 10;
            const int ix = corner - iy * 10;
            const int y = ymin + iy;
            const int x = xmin + ix;
            float acc = 0.0f;
            if ((unsigned)y < (unsigned)h && (unsigned)x < (unsigned)h) {
                const float* v = base + (((size_t)y * h + x) << 8);
                const float4 a = *(const float4*)(v + lane * 4);
                const float4 c = *(const float4*)(v + 128 + lane * 4);
                acc = a.x * f1a.x + a.y * f1a.y + a.z * f1a.z + a.w * f1a.w
                    + c.x * f1b.x + c.y * f1b.y + c.z * f1b.z + c.w * f1b.w;
            }
#pragma unroll
            for (int d = 16; d; d >>= 1)
                acc += __shfl_xor_sync(0xFFFFFFFFu, acc, d);
            if (lane == 0) D[k][corner] = acc;
        }
    }
    __syncthreads();

    // ---- Phase B: taps ----
    if (tid < 4 * NL) {
        const int k = tid / NL;
        const int l = tid - k * NL;
        const int   h   = H8 >> k;
        const float s   = (float)(h - 1) / (float)h;
        const float inv = 1.0f / (float)(1 << k);
        const float ycf = ((float)i + fy) * inv;
        const float xcf = ((float)j + fx) * inv;

        const float py = (ycf + c_dy[l]) * s;
        const float px = (xcf + c_dx[l]) * s;
        const float y0f = floorf(py);
        const float x0f = floorf(px);
        const float wy1 = py - y0f, wy0 = 1.0f - wy1;
        const float wx1 = px - x0f, wx0 = 1.0f - wx1;

        const int ymin = (int)floorf((ycf - 4.0f) * s);
        const int xmin = (int)floorf((xcf - 4.0f) * s);
        const int iy = (int)y0f - ymin;
        const int ix = (int)x0f - xmin;

        const float* Dk = D[k];
        const float d00 = Dk[iy * 10 + ix];
        const float d01 = Dk[iy * 10 + ix + 1];
        const float d10 = Dk[iy * 10 + ix + 10];
        const float d11 = Dk[iy * 10 + ix + 11];
        const float r = wy0 * (wx0 * d00 + wx1 * d01) + wy1 * (wx0 * d10 + wx1 * d11);

        out[(((size_t)b * NPIX + pix) * 4 + k) * NL + l] = r * 0.0625f;  // 1/sqrt(256)
    }
}

// ---------------------------------------------------------------------------
extern "C" void kernel_launch(void* const* d_in, const int* in_sizes, int n_in,
                              void* d_out, int out_size) {
    const float* feat1 = (const float*)d_in[0];
    const float* feat2 = (const float*)d_in[1];
    const float* flow  = (const float*)d_in[2];
    float* out = (float*)d_out;

    dim3 tgrid(NPIX / 32, CH / 32, BATCH);
    dim3 tblk(32, 8);
    transpose_kernel<<<tgrid, tblk>>>(feat1, 0, NPIX);
    transpose_kernel<<<tgrid, tblk>>>(feat2, 1, F2P_PIX);

    // pools: level0 -> 1 -> 2 -> 3
    {
        int ho = 32;
        int threads = BATCH * ho * ho * 64;
        pool_kernel<<<threads / 256, 256>>>(LVL0_OFF, LVL1_OFF, ho);
    }
    {
        int ho = 16;
        int threads = BATCH * ho * ho * 64;
        pool_kernel<<<threads / 256, 256>>>(LVL1_OFF, LVL2_OFF, ho);
    }
    {
        int ho = 8;
        int threads = BATCH * ho * ho * 64;
        pool_kernel<<<threads / 256, 256>>>(LVL2_OFF, LVL3_OFF, ho);
    }

    dim3 lgrid(NPIX, BATCH);
    lookup_kernel<<<lgrid, 256>>>(flow, out);
}

// round 3
// speedup vs baseline: 1.2584x; 1.2584x over previous
#include <cuda_runtime.h>
#include <cstdint>

// Problem constants
#define H8    64
#define W8    64
#define CH    256
#define BATCH 4
#define NPIX  (H8 * W8)          // 4096
#define NL    41                 // diamond taps
#define F2P_PIX 5440             // 4096 + 1024 + 256 + 64 pooled pixels per batch

// Level pixel offsets inside g_f2p (per batch)
#define LVL0_OFF 0
#define LVL1_OFF 4096
#define LVL2_OFF 5120
#define LVL3_OFF 5376

// Scratch: transposed f1 [B][pix][C], pooled+transposed f2 pyramid [B][lvl pix][C]
__device__ __align__(16) float g_f1t[BATCH * NPIX * CH];
__device__ __align__(16) float g_f2p[BATCH * F2P_PIX * CH];

// Diamond offsets (y, x): y=-4..4, x = |y|-4 .. 4-|y|  (41 total)
__constant__ float c_dy[NL] = {
    -4.f,
    -3.f,-3.f,-3.f,
    -2.f,-2.f,-2.f,-2.f,-2.f,
    -1.f,-1.f,-1.f,-1.f,-1.f,-1.f,-1.f,
     0.f, 0.f, 0.f, 0.f, 0.f, 0.f, 0.f, 0.f, 0.f,
     1.f, 1.f, 1.f, 1.f, 1.f, 1.f, 1.f,
     2.f, 2.f, 2.f, 2.f, 2.f,
     3.f, 3.f, 3.f,
     4.f};
__constant__ float c_dx[NL] = {
     0.f,
    -1.f, 0.f, 1.f,
    -2.f,-1.f, 0.f, 1.f, 2.f,
    -3.f,-2.f,-1.f, 0.f, 1.f, 2.f, 3.f,
    -4.f,-3.f,-2.f,-1.f, 0.f, 1.f, 2.f, 3.f, 4.f,
    -3.f,-2.f,-1.f, 0.f, 1.f, 2.f, 3.f,
    -2.f,-1.f, 0.f, 1.f, 2.f,
    -1.f, 0.f, 1.f,
     0.f};

// ---------------------------------------------------------------------------
// Kernel 1: transpose [B][C][4096] -> [B][4096][C]   (which=0 -> g_f1t, 1 -> g_f2p lvl0)
// ---------------------------------------------------------------------------
__global__ void transpose_kernel(const float* __restrict__ in, int which, int out_pix_stride) {
    __shared__ float tile[32][33];
    float* outp = which ? g_f2p : g_f1t;
    int b  = blockIdx.z;
    int p0 = blockIdx.x * 32;
    int c0 = blockIdx.y * 32;
    const float* inb = in + (size_t)b * CH * NPIX;
    float* outb = outp + (size_t)b * out_pix_stride * CH;
    int tx = threadIdx.x, ty = threadIdx.y;
#pragma unroll
    for (int r = 0; r < 32; r += 8)
        tile[ty + r][tx] = inb[(size_t)(c0 + ty + r) * NPIX + (p0 + tx)];
    __syncthreads();
#pragma unroll
    for (int r = 0; r < 32; r += 8)
        outb[(size_t)(p0 + ty + r) * CH + (c0 + tx)] = tile[tx][ty + r];
}

// ---------------------------------------------------------------------------
// Kernel 2: 2x2 avg pool in [y][x][C] layout (within g_f2p), per batch.
// ---------------------------------------------------------------------------
__global__ void pool_kernel(int in_off, int out_off, int ho) {
    int idx = blockIdx.x * blockDim.x + threadIdx.x;
    int c4   = idx & 63;
    int rest = idx >> 6;
    int x = rest % ho; rest /= ho;
    int y = rest % ho;
    int b = rest / ho;
    int wi = ho * 2;
    const float4* inp = (const float4*)g_f2p;
    float4*       out4 = (float4*)g_f2p;
    size_t base = ((size_t)b * F2P_PIX + in_off + (size_t)(2 * y) * wi + 2 * x) * 64 + c4;
    float4 v00 = inp[base];
    float4 v01 = inp[base + 64];
    float4 v10 = inp[base + (size_t)wi * 64];
    float4 v11 = inp[base + (size_t)wi * 64 + 64];
    float4 o;
    o.x = 0.25f * (v00.x + v01.x + v10.x + v11.x);
    o.y = 0.25f * (v00.y + v01.y + v10.y + v11.y);
    o.z = 0.25f * (v00.z + v01.z + v10.z + v11.z);
    o.w = 0.25f * (v00.w + v01.w + v10.w + v11.w);
    out4[((size_t)b * F2P_PIX + out_off + (size_t)y * ho + x) * 64 + c4] = o;
}

// ---------------------------------------------------------------------------
// Kernel 3: fused lookup.
// Block = 4x4 pixel tile (16 warps, warp-per-pixel). Each warp:
//   Phase A (per level): build 100-bit mask of corners actually touched by the
//     41 taps, compute dot(f1, f2[corner]) only for set corners -> smem table.
//     All warps process the same level concurrently (syncthreads between
//     levels) so overlapping windows hit in L1.
//   Phase B: 164 taps bilinearly combine 4 table entries each.
// ---------------------------------------------------------------------------
__global__ void __launch_bounds__(512) lookup_kernel(const float* __restrict__ flow,
                                                     float* __restrict__ out) {
    const int tid  = threadIdx.x;
    const int lane = tid & 31;
    const int warp = tid >> 5;            // 0..15 -> pixel within tile

    const int tile = blockIdx.x;          // 0..255
    const int bb   = blockIdx.y;
    const int i = ((tile >> 4) << 2) + (warp >> 2);
    const int j = ((tile & 15) << 2) + (warp & 3);
    const int pix = i * W8 + j;

    __shared__ float D[16][4][100];
    __shared__ float s_dy[NL], s_dx[NL];
    if (tid < NL) { s_dy[tid] = c_dy[tid]; s_dx[tid] = c_dx[tid]; }
    __syncthreads();

    const float fy = flow[((size_t)(bb * 2 + 0) * H8 + i) * W8 + j];
    const float fx = flow[((size_t)(bb * 2 + 1) * H8 + i) * W8 + j];
    const float fi = (float)i, fj = (float)j;

    // f1 vector: lane holds channels [4*lane..] and [128+4*lane..]
    const float* f1v = g_f1t + ((size_t)bb * NPIX + pix) * CH;
    const float4 f1a = *(const float4*)(f1v + 4 * lane);
    const float4 f1b = *(const float4*)(f1v + 128 + 4 * lane);

    const int lvl_off[4] = {LVL0_OFF, LVL1_OFF, LVL2_OFF, LVL3_OFF};

    // ---- Phase A ----
    for (int k = 0; k < 4; k++) {
        const int   hh  = H8 >> k;
        const float s   = (float)(hh - 1) / (float)hh;
        const float inv = 1.0f / (float)(1 << k);
        const float ycf = (fi + fy) * inv;
        const float xcf = (fj + fx) * inv;
        const int ymin = (int)floorf((ycf - 4.0f) * s);
        const int xmin = (int)floorf((xcf - 4.0f) * s);

        // Build needed-corner mask (bits 0..99 of 128-bit mask).
        unsigned long long m0 = 0ull, m1 = 0ull;
#pragma unroll
        for (int r = 0; r < 2; r++) {
            int t = lane + r * 32;
            if (t < NL) {
                float py = (ycf + s_dy[t]) * s;
                float px = (xcf + s_dx[t]) * s;
                int iy = (int)floorf(py) - ymin;       // 0..8
                int ix = (int)floorf(px) - xmin;       // 0..8
                int p  = iy * 10 + ix;                  // <= 88
                // corners p, p+1, p+10, p+11 (all <= 99)
#pragma unroll
                for (int q = 0; q < 2; q++) {
                    int pp = p + q * 10;
                    int sh = pp & 63;
                    unsigned long long pair = 3ull << sh;
                    if (pp < 64) {
                        m0 |= pair;
                        if (sh == 63) m1 |= 1ull;       // pair spans the boundary
                    } else {
                        m1 |= pair;                     // sh <= 46 here, no span
                    }
                }
            }
        }
        // OR-reduce mask across the warp (32-bit redux x4)
        unsigned a0 = __reduce_or_sync(0xFFFFFFFFu, (unsigned)m0);
        unsigned a1 = __reduce_or_sync(0xFFFFFFFFu, (unsigned)(m0 >> 32));
        unsigned a2 = __reduce_or_sync(0xFFFFFFFFu, (unsigned)m1);
        unsigned a3 = __reduce_or_sync(0xFFFFFFFFu, (unsigned)(m1 >> 32));
        m0 = (unsigned long long)a0 | ((unsigned long long)a1 << 32);
        m1 = (unsigned long long)a2 | ((unsigned long long)a3 << 32);

        const float* base = g_f2p + ((size_t)bb * F2P_PIX + lvl_off[k]) * CH;
        float* Dk = &D[warp][k][0];

#pragma unroll
        for (int wsel = 0; wsel < 2; wsel++) {
            unsigned long long bits = wsel ? m1 : m0;
            const int cbase = wsel * 64;
            while (bits) {
                int c = __ffsll((long long)bits) - 1;
                bits &= bits - 1;
                const int corner = cbase + c;
                const int iy = corner / 10;
                const int ix = corner - iy * 10;
                const int y = ymin + iy;
                const int x = xmin + ix;
                if ((unsigned)y < (unsigned)hh && (unsigned)x < (unsigned)hh) {
                    const float* v = base + (((size_t)(y * hh + x)) << 8);
                    const float4 a  = *(const float4*)(v + 4 * lane);
                    const float4 c4 = *(const float4*)(v + 128 + 4 * lane);
                    float acc = a.x * f1a.x + a.y * f1a.y + a.z * f1a.z + a.w * f1a.w
                              + c4.x * f1b.x + c4.y * f1b.y + c4.z * f1b.z + c4.w * f1b.w;
#pragma unroll
                    for (int d = 16; d; d >>= 1)
                        acc += __shfl_xor_sync(0xFFFFFFFFu, acc, d);
                    if (lane == 0) Dk[corner] = acc;
                } else {
                    if (lane == 0) Dk[corner] = 0.0f;
                }
            }
        }
        __syncthreads();   // keep all warps on the same level (L1 locality)
    }

    __syncwarp();

    // ---- Phase B: taps ----
    for (int t = lane; t < 4 * NL; t += 32) {
        const int k = t / NL;
        const int l = t - k * NL;
        const int   hh  = H8 >> k;
        const float s   = (float)(hh - 1) / (float)hh;
        const float inv = 1.0f / (float)(1 << k);
        const float ycf = (fi + fy) * inv;
        const float xcf = (fj + fx) * inv;

        const float py = (ycf + s_dy[l]) * s;
        const float px = (xcf + s_dx[l]) * s;
        const float y0f = floorf(py);
        const float x0f = floorf(px);
        const float wy1 = py - y0f, wy0 = 1.0f - wy1;
        const float wx1 = px - x0f, wx0 = 1.0f - wx1;

        const int ymin = (int)floorf((ycf - 4.0f) * s);
        const int xmin = (int)floorf((xcf - 4.0f) * s);
        const int iy = (int)y0f - ymin;
        const int ix = (int)x0f - xmin;

        const float* Dk = D[warp][k];
        const float d00 = Dk[iy * 10 + ix];
        const float d01 = Dk[iy * 10 + ix + 1];
        const float d10 = Dk[iy * 10 + ix + 10];
        const float d11 = Dk[iy * 10 + ix + 11];
        const float r = wy0 * (wx0 * d00 + wx1 * d01) + wy1 * (wx0 * d10 + wx1 * d11);

        out[(((size_t)bb * NPIX + pix) * 4 + k) * NL + l] = r * 0.0625f;  // 1/sqrt(256)
    }
}

// ---------------------------------------------------------------------------
extern "C" void kernel_launch(void* const* d_in, const int* in_sizes, int n_in,
                              void* d_out, int out_size) {
    const float* feat1 = (const float*)d_in[0];
    const float* feat2 = (const float*)d_in[1];
    const float* flow  = (const float*)d_in[2];
    float* out = (float*)d_out;

    dim3 tgrid(NPIX / 32, CH / 32, BATCH);
    dim3 tblk(32, 8);
    transpose_kernel<<<tgrid, tblk>>>(feat1, 0, NPIX);
    transpose_kernel<<<tgrid, tblk>>>(feat2, 1, F2P_PIX);

    {
        int ho = 32;
        int threads = BATCH * ho * ho * 64;
        pool_kernel<<<threads / 256, 256>>>(LVL0_OFF, LVL1_OFF, ho);
    }
    {
        int ho = 16;
        int threads = BATCH * ho * ho * 64;
        pool_kernel<<<threads / 256, 256>>>(LVL1_OFF, LVL2_OFF, ho);
    }
    {
        int ho = 8;
        int threads = BATCH * ho * ho * 64;
        pool_kernel<<<threads / 256, 256>>>(LVL2_OFF, LVL3_OFF, ho);
    }

    dim3 lgrid(256, BATCH);
    lookup_kernel<<<lgrid, 512>>>(flow, out);
}

// round 4
// speedup vs baseline: 1.6558x; 1.3158x over previous
#include <cuda_runtime.h>
#include <cstdint>

// Problem constants
#define H8    64
#define W8    64
#define CH    256
#define BATCH 4
#define NPIX  (H8 * W8)          // 4096
#define NL    41                 // diamond taps
#define F2P_PIX 5440             // 4096 + 1024 + 256 + 64 pooled pixels per batch

// Level pixel offsets inside g_f2p (per batch)
#define LVL0_OFF 0
#define LVL1_OFF 4096
#define LVL2_OFF 5120
#define LVL3_OFF 5376

// Scratch: transposed f1 [B][pix][C], pooled+transposed f2 pyramid [B][lvl pix][C]
__device__ __align__(16) float g_f1t[BATCH * NPIX * CH];
__device__ __align__(16) float g_f2p[BATCH * F2P_PIX * CH];

// Diamond offsets (y, x): y=-4..4, x = |y|-4 .. 4-|y|  (41 total)
__constant__ float c_dy[NL] = {
    -4.f,
    -3.f,-3.f,-3.f,
    -2.f,-2.f,-2.f,-2.f,-2.f,
    -1.f,-1.f,-1.f,-1.f,-1.f,-1.f,-1.f,
     0.f, 0.f, 0.f, 0.f, 0.f, 0.f, 0.f, 0.f, 0.f,
     1.f, 1.f, 1.f, 1.f, 1.f, 1.f, 1.f,
     2.f, 2.f, 2.f, 2.f, 2.f,
     3.f, 3.f, 3.f,
     4.f};
__constant__ float c_dx[NL] = {
     0.f,
    -1.f, 0.f, 1.f,
    -2.f,-1.f, 0.f, 1.f, 2.f,
    -3.f,-2.f,-1.f, 0.f, 1.f, 2.f, 3.f,
    -4.f,-3.f,-2.f,-1.f, 0.f, 1.f, 2.f, 3.f, 4.f,
    -3.f,-2.f,-1.f, 0.f, 1.f, 2.f, 3.f,
    -2.f,-1.f, 0.f, 1.f, 2.f,
    -1.f, 0.f, 1.f,
     0.f};

// ---------------------------------------------------------------------------
// Kernel 1: transpose [B][C][4096] -> [B][4096][C]
// ---------------------------------------------------------------------------
__global__ void transpose_kernel(const float* __restrict__ in, int which, int out_pix_stride) {
    __shared__ float tile[32][33];
    float* outp = which ? g_f2p : g_f1t;
    int b  = blockIdx.z;
    int p0 = blockIdx.x * 32;
    int c0 = blockIdx.y * 32;
    const float* inb = in + (size_t)b * CH * NPIX;
    float* outb = outp + (size_t)b * out_pix_stride * CH;
    int tx = threadIdx.x, ty = threadIdx.y;
#pragma unroll
    for (int r = 0; r < 32; r += 8)
        tile[ty + r][tx] = inb[(size_t)(c0 + ty + r) * NPIX + (p0 + tx)];
    __syncthreads();
#pragma unroll
    for (int r = 0; r < 32; r += 8)
        outb[(size_t)(p0 + ty + r) * CH + (c0 + tx)] = tile[tx][ty + r];
}

// ---------------------------------------------------------------------------
// Kernel 2: 2x2 avg pool in [y][x][C] layout (within g_f2p), per batch.
// ---------------------------------------------------------------------------
__global__ void pool_kernel(int in_off, int out_off, int ho) {
    int idx = blockIdx.x * blockDim.x + threadIdx.x;
    int c4   = idx & 63;
    int rest = idx >> 6;
    int x = rest % ho; rest /= ho;
    int y = rest % ho;
    int b = rest / ho;
    int wi = ho * 2;
    const float4* inp = (const float4*)g_f2p;
    float4*       out4 = (float4*)g_f2p;
    size_t base = ((size_t)b * F2P_PIX + in_off + (size_t)(2 * y) * wi + 2 * x) * 64 + c4;
    float4 v00 = inp[base];
    float4 v01 = inp[base + 64];
    float4 v10 = inp[base + (size_t)wi * 64];
    float4 v11 = inp[base + (size_t)wi * 64 + 64];
    float4 o;
    o.x = 0.25f * (v00.x + v01.x + v10.x + v11.x);
    o.y = 0.25f * (v00.y + v01.y + v10.y + v11.y);
    o.z = 0.25f * (v00.z + v01.z + v10.z + v11.z);
    o.w = 0.25f * (v00.w + v01.w + v10.w + v11.w);
    out4[((size_t)b * F2P_PIX + out_off + (size_t)y * ho + x) * 64 + c4] = o;
}

// ---------------------------------------------------------------------------
// Kernel 3: fused lookup.
// Block = 4x4 pixel tile (16 warps, warp-per-pixel).
// Per level:
//   1. build 100-bit needed-corner mask from the 41 taps (warp OR-reduce)
//   2. ballot-compact in-bounds set bits into a smem corner list
//   3. quad loop: 8 lanes per corner, 4 corners per step. Lane accumulates 32
//      channels (8 float4, 128B contiguous per corner group), 3-shuffle reduce.
// Phase B: 164 taps bilinearly combine 4 corner-dot table entries each.
// ---------------------------------------------------------------------------
__global__ void __launch_bounds__(512) lookup_kernel(const float* __restrict__ flow,
                                                     float* __restrict__ out) {
    const int tid  = threadIdx.x;
    const int lane = tid & 31;
    const int warp = tid >> 5;            // 0..15 -> pixel within tile

    const int tile = blockIdx.x;          // 0..255
    const int bb   = blockIdx.y;
    const int i = ((tile >> 4) << 2) + (warp >> 2);
    const int j = ((tile & 15) << 2) + (warp & 3);
    const int pix = i * W8 + j;

    __shared__ float D[16][4][100];
    __shared__ short s_list[16][104];
    __shared__ float s_dy[NL], s_dx[NL];
    if (tid < NL) { s_dy[tid] = c_dy[tid]; s_dx[tid] = c_dx[tid]; }

    // Zero this warp's D table (corners never computed must read as 0).
    {
        float* dw = &D[warp][0][0];
        for (int t = lane; t < 400; t += 32) dw[t] = 0.0f;
    }
    __syncthreads();

    const float fy = flow[((size_t)(bb * 2 + 0) * H8 + i) * W8 + j];
    const float fx = flow[((size_t)(bb * 2 + 1) * H8 + i) * W8 + j];
    const float fi = (float)i, fj = (float)j;

    // f1 slice: lane (s = lane&7) holds channels {t*32 + s*4 .. +3} for t=0..7
    const int s4 = (lane & 7) << 2;
    const int g  = lane >> 3;             // corner group 0..3
    const float* f1v = g_f1t + ((size_t)bb * NPIX + pix) * CH;
    float4 f1r[8];
#pragma unroll
    for (int t = 0; t < 8; t++)
        f1r[t] = *(const float4*)(f1v + t * 32 + s4);

    const int lvl_off[4] = {LVL0_OFF, LVL1_OFF, LVL2_OFF, LVL3_OFF};

    for (int k = 0; k < 4; k++) {
        const int   hh  = H8 >> k;
        const float s   = (float)(hh - 1) / (float)hh;
        const float inv = 1.0f / (float)(1 << k);
        const float ycf = (fi + fy) * inv;
        const float xcf = (fj + fx) * inv;
        const int ymin = (int)floorf((ycf - 4.0f) * s);
        const int xmin = (int)floorf((xcf - 4.0f) * s);

        // ---- 1. needed-corner mask (bits 0..99) ----
        unsigned long long m0 = 0ull, m1 = 0ull;
#pragma unroll
        for (int r = 0; r < 2; r++) {
            int t = lane + r * 32;
            if (t < NL) {
                float py = (ycf + s_dy[t]) * s;
                float px = (xcf + s_dx[t]) * s;
                int iy = (int)floorf(py) - ymin;       // 0..8
                int ix = (int)floorf(px) - xmin;       // 0..8
                int p  = iy * 10 + ix;                  // <= 88
#pragma unroll
                for (int q = 0; q < 2; q++) {
                    int pp = p + q * 10;
                    int sh = pp & 63;
                    unsigned long long pair = 3ull << sh;
                    if (pp < 64) {
                        m0 |= pair;
                        if (sh == 63) m1 |= 1ull;
                    } else {
                        m1 |= pair;
                    }
                }
            }
        }
        unsigned a0 = __reduce_or_sync(0xFFFFFFFFu, (unsigned)m0);
        unsigned a1 = __reduce_or_sync(0xFFFFFFFFu, (unsigned)(m0 >> 32));
        unsigned a2 = __reduce_or_sync(0xFFFFFFFFu, (unsigned)m1);
        unsigned a3 = __reduce_or_sync(0xFFFFFFFFu, (unsigned)(m1 >> 32));

        // ---- 2. ballot-compact in-bounds corners into list ----
        short* lst = s_list[warp];
        int n = 0;
        unsigned chunks[4] = {a0, a1, a2, a3};
#pragma unroll
        for (int r = 0; r < 4; r++) {
            int p = r * 32 + lane;
            unsigned bit = (chunks[r] >> lane) & 1u;
            if (bit) {
                int iy = (p * 205) >> 11;              // p/10, exact for p<1024
                int ix = p - iy * 10;
                int y = ymin + iy, x = xmin + ix;
                if ((unsigned)y >= (unsigned)hh || (unsigned)x >= (unsigned)hh) bit = 0;
            }
            unsigned ball = __ballot_sync(0xFFFFFFFFu, bit);
            if (bit) lst[n + __popc(ball & ((1u << lane) - 1u))] = (short)p;
            n += __popc(ball);
        }
        __syncwarp();

        // ---- 3. corner-quad dot loop ----
        const float* base = g_f2p + ((size_t)bb * F2P_PIX + lvl_off[k]) * CH;
        float* Dk = &D[warp][k][0];

        for (int q = 0; q < n; q += 4) {
            int idx = q + g;
            int cidx = idx < n ? idx : n - 1;
            const int cid = lst[cidx];
            const int iy = (cid * 205) >> 11;
            const int ix = cid - iy * 10;
            const float* v = base + (((size_t)((ymin + iy) * hh + (xmin + ix))) << 8) + s4;

            float acc0 = 0.0f, acc1 = 0.0f;
#pragma unroll
            for (int t = 0; t < 8; t += 2) {
                float4 u = *(const float4*)(v + t * 32);
                float4 w = *(const float4*)(v + t * 32 + 32);
                acc0 = fmaf(u.x, f1r[t].x, acc0);
                acc0 = fmaf(u.y, f1r[t].y, acc0);
                acc0 = fmaf(u.z, f1r[t].z, acc0);
                acc0 = fmaf(u.w, f1r[t].w, acc0);
                acc1 = fmaf(w.x, f1r[t + 1].x, acc1);
                acc1 = fmaf(w.y, f1r[t + 1].y, acc1);
                acc1 = fmaf(w.z, f1r[t + 1].z, acc1);
                acc1 = fmaf(w.w, f1r[t + 1].w, acc1);
            }
            float acc = acc0 + acc1;
            acc += __shfl_xor_sync(0xFFFFFFFFu, acc, 1);
            acc += __shfl_xor_sync(0xFFFFFFFFu, acc, 2);
            acc += __shfl_xor_sync(0xFFFFFFFFu, acc, 4);
            if ((lane & 7) == 0 && idx < n) Dk[cid] = acc;
        }
        __syncthreads();   // keep all warps on the same level (L1 locality)
    }

    // ---- Phase B: taps ----
    for (int t = lane; t < 4 * NL; t += 32) {
        const int k = t / NL;
        const int l = t - k * NL;
        const int   hh  = H8 >> k;
        const float s   = (float)(hh - 1) / (float)hh;
        const float inv = 1.0f / (float)(1 << k);
        const float ycf = (fi + fy) * inv;
        const float xcf = (fj + fx) * inv;

        const float py = (ycf + s_dy[l]) * s;
        const float px = (xcf + s_dx[l]) * s;
        const float y0f = floorf(py);
        const float x0f = floorf(px);
        const float wy1 = py - y0f, wy0 = 1.0f - wy1;
        const float wx1 = px - x0f, wx0 = 1.0f - wx1;

        const int ymin = (int)floorf((ycf - 4.0f) * s);
        const int xmin = (int)floorf((xcf - 4.0f) * s);
        const int iy = (int)y0f - ymin;
        const int ix = (int)x0f - xmin;

        const float* Dk = D[warp][k];
        const float d00 = Dk[iy * 10 + ix];
        const float d01 = Dk[iy * 10 + ix + 1];
        const float d10 = Dk[iy * 10 + ix + 10];
        const float d11 = Dk[iy * 10 + ix + 11];
        const float r = wy0 * (wx0 * d00 + wx1 * d01) + wy1 * (wx0 * d10 + wx1 * d11);

        out[(((size_t)bb * NPIX + pix) * 4 + k) * NL + l] = r * 0.0625f;  // 1/sqrt(256)
    }
}

// ---------------------------------------------------------------------------
extern "C" void kernel_launch(void* const* d_in, const int* in_sizes, int n_in,
                              void* d_out, int out_size) {
    const float* feat1 = (const float*)d_in[0];
    const float* feat2 = (const float*)d_in[1];
    const float* flow  = (const float*)d_in[2];
    float* out = (float*)d_out;

    dim3 tgrid(NPIX / 32, CH / 32, BATCH);
    dim3 tblk(32, 8);
    transpose_kernel<<<tgrid, tblk>>>(feat1, 0, NPIX);
    transpose_kernel<<<tgrid, tblk>>>(feat2, 1, F2P_PIX);

    {
        int ho = 32;
        int threads = BATCH * ho * ho * 64;
        pool_kernel<<<threads / 256, 256>>>(LVL0_OFF, LVL1_OFF, ho);
    }
    {
        int ho = 16;
        int threads = BATCH * ho * ho * 64;
        pool_kernel<<<threads / 256, 256>>>(LVL1_OFF, LVL2_OFF, ho);
    }
    {
        int ho = 8;
        int threads = BATCH * ho * ho * 64;
        pool_kernel<<<threads / 256, 256>>>(LVL2_OFF, LVL3_OFF, ho);
    }

    dim3 lgrid(256, BATCH);
    lookup_kernel<<<lgrid, 512>>>(flow, out);
}